// round 16
// baseline (speedup 1.0000x reference)
#include <cuda_runtime.h>
#include <cuda_bf16.h>
#include <cstdint>

// x: [32,2048] int32 ids in [0,100000); W: [256,100000] f32 (EMBED-major);
// b: [256] f32; out: [65536,256] f32 = W[:, x[t]] + b.
//
// 3-kernel PDL chain:
// K1 hist_rank    : 1 tok/thread, 256 CTAs (latency-optimized: max chains in
//                   flight, 1 atomic deep): rank[t]=atomicAdd(bins[id>>5],1)
// K2 scan_scatter : every CTA redundantly shuffle-scans the 3125 bins into
//                   smem, then scatters its 1024 tokens atomic-free.
// K3 gather       : 32 sorted tokens x 128 dims per CTA; first 13 CTAs also
//                   re-zero g_bins (PDL-ordered after K2's reads). Coalesced
//                   strided LDG -> STS.128 tile (stride 132) -> LDS.128+bias
//                   -> STG.128 evict-first contiguous rows.
static constexpr int VOCAB = 100000;
static constexpr int EMBED = 256;
static constexpr int NTOK  = 32 * 2048;            // 65536
static constexpr int NBINS = (VOCAB + 31) / 32;    // 3125
static constexpr int HDIM  = 128;
static constexpr int TSTR  = 132;
static constexpr int SCTAS = NTOK / 1024;          // 64 scatter CTAs (4 tok/thr)
static constexpr int BPT   = 13;                   // bins per thread (256*13>=3125)

__device__ int  g_bins[NBINS];     // zero at load; gather re-zeroes each launch
__device__ int  g_rank[NTOK];
__device__ int2 g_sorted[NTOK];

__device__ __forceinline__ int clamp_id(int v) {
    return min(max(v, 0), VOCAB - 1);
}

// ---- K1: histogram + rank, 1 token/thread (latency-optimized) ------------
__global__ __launch_bounds__(256) void hist_rank_kernel(const int* __restrict__ x) {
    const int t = blockIdx.x * 256 + threadIdx.x;  // 0..65535
    const int v = clamp_id(__ldg(&x[t]));
    g_rank[t] = atomicAdd(&g_bins[v >> 5], 1);     // single-atomic chain
}

// ---- K2: redundant per-CTA scan + scatter (PDL consumer) -----------------
__global__ __launch_bounds__(256) void scan_scatter_kernel(const int* __restrict__ x)
{
    __shared__ int s_offs[NBINS];                  // 12.5 KB
    __shared__ int warp_tot[8];

    const int tid  = threadIdx.x;
    const int lane = tid & 31;
    const int wid  = tid >> 5;
    const int t0   = (blockIdx.x * 256 + tid) * 4;

    // independent input load before the dependency sync
    const int4 xv = *reinterpret_cast<const int4*>(x + t0);
    const int v[4] = { clamp_id(xv.x), clamp_id(xv.y), clamp_id(xv.z), clamp_id(xv.w) };

#if __CUDA_ARCH__ >= 900
    cudaGridDependencySynchronize();               // wait for K1 (bins, rank)
#endif

    // redundant exclusive scan of 3125 bins -> s_offs (identical in all CTAs)
    int c[BPT]; int s = 0;
#pragma unroll
    for (int k = 0; k < BPT; ++k) {
        const int idx = tid * BPT + k;
        c[k] = (idx < NBINS) ? __ldcg(&g_bins[idx]) : 0;   // L2-hot broadcast
        s += c[k];
    }
    int incl = s;
#pragma unroll
    for (int off = 1; off < 32; off <<= 1) {
        int t = __shfl_up_sync(0xffffffff, incl, off);
        if (lane >= off) incl += t;
    }
    if (lane == 31) warp_tot[wid] = incl;
    __syncthreads();
    if (wid == 0 && lane < 8) {                    // scan 8 warp totals
        int wv = warp_tot[lane];
        int wi = wv;
#pragma unroll
        for (int off = 1; off < 8; off <<= 1) {
            int t = __shfl_up_sync(0x000000ff, wi, off);
            if (lane >= off) wi += t;
        }
        warp_tot[lane] = wi - wv;                  // exclusive base per warp
    }
    __syncthreads();
    int base = warp_tot[wid] + (incl - s);
#pragma unroll
    for (int k = 0; k < BPT; ++k) {
        const int idx = tid * BPT + k;
        if (idx < NBINS) s_offs[idx] = base;
        base += c[k];
    }
    __syncthreads();

    // scatter this CTA's 1024 tokens, atomic-free
    const int4 rv = *reinterpret_cast<const int4*>(g_rank + t0);
    const int rk[4] = { rv.x, rv.y, rv.z, rv.w };
#pragma unroll
    for (int k = 0; k < 4; ++k) {
        const int pos = s_offs[v[k] >> 5] + rk[k];
        __stcg(&g_sorted[pos], make_int2(v[k], t0 + k));
    }
}

// ---- K3: gather (PDL consumer) + bins re-zero ----------------------------
__global__ __launch_bounds__(256) void gather_kernel(
    const float* __restrict__ W,
    const float* __restrict__ bias,
    float*       __restrict__ out)
{
    __shared__ __align__(16) float tile[32][TSTR];
    __shared__ int s_id[32], s_tok[32];

    const int tid   = threadIdx.x;
    const int group = blockIdx.x >> 1;
    const int half  = blockIdx.x & 1;
    const int dim0  = half * HDIM;
    const int w = tid >> 5;          // warp -> dims [16w,16w+16) of half
    const int l = tid & 31;          // lane -> sorted token

    // independent: bias load before the dependency sync
    const float4 bv = __ldg(reinterpret_cast<const float4*>(bias) + half * 32 + l);

#if __CUDA_ARCH__ >= 900
    cudaGridDependencySynchronize();               // wait for g_sorted (K2)
#endif

    // restore invariant: first 13 CTAs zero g_bins (after K2's reads, by PDL)
    if (blockIdx.x < (NBINS + 255) / 256) {
        const int idx = blockIdx.x * 256 + tid;
        if (idx < NBINS) __stcg(&g_bins[idx], 0);
    }

    if (tid < 32) {
        int2 p = g_sorted[group * 32 + tid];
        s_id[tid]  = p.x;
        s_tok[tid] = p.y;
    }
    __syncthreads();

    const int vid = s_id[l];
    const float* wp = W + (size_t)(dim0 + w * 16) * VOCAB + (size_t)vid;
    float rr[16];
#pragma unroll
    for (int j = 0; j < 16; ++j)
        rr[j] = __ldg(wp + (size_t)j * VOCAB);     // coalesced via sort

#pragma unroll
    for (int j = 0; j < 4; ++j) {
        float4 v4 = make_float4(rr[4*j], rr[4*j+1], rr[4*j+2], rr[4*j+3]);
        *reinterpret_cast<float4*>(&tile[l][w * 16 + 4 * j]) = v4;
    }
    __syncthreads();

#pragma unroll
    for (int i = 0; i < 4; ++i) {
        const int t    = w * 4 + i;
        const int orig = s_tok[t];
        float4 v4 = *reinterpret_cast<const float4*>(&tile[t][4 * l]);
        v4.x += bv.x; v4.y += bv.y; v4.z += bv.z; v4.w += bv.w;
        __stcs(reinterpret_cast<float4*>(out + (size_t)orig * EMBED + dim0) + l, v4);
    }
}

// ---- host: PDL-chained launches ------------------------------------------
template <typename K, typename... Args>
static void launch_pdl(K kernel, dim3 grid, dim3 block, Args... args)
{
    cudaLaunchAttribute attr;
    attr.id = cudaLaunchAttributeProgrammaticStreamSerialization;
    attr.val.programmaticStreamSerializationAllowed = 1;
    cudaLaunchConfig_t cfg = {};
    cfg.gridDim  = grid;
    cfg.blockDim = block;
    cfg.attrs    = &attr;
    cfg.numAttrs = 1;
    cfg.stream   = 0;
    cudaLaunchKernelEx(&cfg, kernel, args...);
}

extern "C" void kernel_launch(void* const* d_in, const int* in_sizes, int n_in,
                              void* d_out, int out_size)
{
    const int*   x    = (const int*)d_in[0];
    const float* W    = (const float*)d_in[1];
    const float* bias = (const float*)d_in[2];
    float*       out  = (float*)d_out;

    hist_rank_kernel<<<NTOK / 256, 256>>>(x);      // 256 CTAs, 1 tok/thread
    launch_pdl(scan_scatter_kernel, dim3(SCTAS),           dim3(256), x);
    launch_pdl(gather_kernel,       dim3((NTOK / 32) * 2), dim3(256), W, bias, out);
}

// round 17
// speedup vs baseline: 1.1520x; 1.1520x over previous
#include <cuda_runtime.h>
#include <cuda_bf16.h>
#include <cstdint>

// x: [32,2048] int32 ids in [0,100000); W: [256,100000] f32 (EMBED-major);
// b: [256] f32; out: [65536,256] f32 = W[:, x[t]] + b.
//
// 3-kernel PDL chain, 4x-replicated histogram to cut L2 same-address
// atomic serialization (hist was contention-bound: shape-invariant 7-8us):
// K1 hist_rank    : CTA b atomics into bin replica r=b&3 (replica-major
//                   layout -> distinct L2 partitions); rank = return value.
// K2 scan_scatter : every CTA redundantly scans all 4 replicas of the 3125
//                   bins; stores offsets SPECIALIZED to its own replica
//                   (base[bin] + sum of earlier replicas) -> 12.5KB smem;
//                   then scatters its 1024 tokens atomic-free.
// K3 gather       : 32 sorted tokens x 128 dims per CTA; first 49 CTAs also
//                   re-zero all 4*3125 bins (PDL-ordered after K2 reads).
static constexpr int VOCAB = 100000;
static constexpr int EMBED = 256;
static constexpr int NTOK  = 32 * 2048;            // 65536
static constexpr int NBINS = (VOCAB + 31) / 32;    // 3125
static constexpr int NREP  = 4;                    // histogram replicas
static constexpr int HDIM  = 128;
static constexpr int TSTR  = 132;
static constexpr int SCTAS = NTOK / 1024;          // 64 hist/scatter CTAs
static constexpr int BPT   = 13;                   // bins per thread (256*13>=3125)

__device__ int  g_bins[NREP * NBINS];  // zero at load; gather re-zeroes
__device__ int  g_rank[NTOK];
__device__ int2 g_sorted[NTOK];

__device__ __forceinline__ int clamp_id(int v) {
    return min(max(v, 0), VOCAB - 1);
}

// ---- K1: histogram + rank into replica (blockIdx & 3) --------------------
__global__ __launch_bounds__(256) void hist_rank_kernel(const int* __restrict__ x) {
    const int t0  = (blockIdx.x * 256 + threadIdx.x) * 4;
    int* bins = g_bins + (blockIdx.x & (NREP - 1)) * NBINS;  // replica-major
    const int4 xv = *reinterpret_cast<const int4*>(x + t0);
    const int v0 = clamp_id(xv.x), v1 = clamp_id(xv.y);
    const int v2 = clamp_id(xv.z), v3 = clamp_id(xv.w);
    int4 r;
    r.x = atomicAdd(&bins[v0 >> 5], 1);            // 4 independent atomics
    r.y = atomicAdd(&bins[v1 >> 5], 1);
    r.z = atomicAdd(&bins[v2 >> 5], 1);
    r.w = atomicAdd(&bins[v3 >> 5], 1);
    *reinterpret_cast<int4*>(g_rank + t0) = r;
}

// ---- K2: redundant scan (replica-specialized) + scatter (PDL consumer) ---
__global__ __launch_bounds__(256) void scan_scatter_kernel(const int* __restrict__ x)
{
    __shared__ int s_offs[NBINS];                  // 12.5 KB, own-replica offsets
    __shared__ int warp_tot[8];

    const int tid  = threadIdx.x;
    const int lane = tid & 31;
    const int wid  = tid >> 5;
    const int rep  = blockIdx.x & (NREP - 1);      // matches hist CTA's replica
    const int t0   = (blockIdx.x * 256 + tid) * 4;

    // independent input load before the dependency sync
    const int4 xv = *reinterpret_cast<const int4*>(x + t0);
    const int v[4] = { clamp_id(xv.x), clamp_id(xv.y), clamp_id(xv.z), clamp_id(xv.w) };

#if __CUDA_ARCH__ >= 900
    cudaGridDependencySynchronize();               // wait for K1 (bins, rank)
#endif

    // scan all replicas; keep per-bin total and own-replica prefix
    int tot[BPT], rp[BPT];
    int s = 0;
#pragma unroll
    for (int k = 0; k < BPT; ++k) {
        const int idx = tid * BPT + k;
        int c0 = 0, c1 = 0, c2 = 0, c3 = 0;
        if (idx < NBINS) {
            c0 = __ldcg(&g_bins[0 * NBINS + idx]); // L2-hot broadcast
            c1 = __ldcg(&g_bins[1 * NBINS + idx]);
            c2 = __ldcg(&g_bins[2 * NBINS + idx]);
            c3 = __ldcg(&g_bins[3 * NBINS + idx]);
        }
        tot[k] = c0 + c1 + c2 + c3;
        rp[k]  = (rep > 0 ? c0 : 0) + (rep > 1 ? c1 : 0) + (rep > 2 ? c2 : 0);
        s += tot[k];
    }
    int incl = s;
#pragma unroll
    for (int off = 1; off < 32; off <<= 1) {
        int t = __shfl_up_sync(0xffffffff, incl, off);
        if (lane >= off) incl += t;
    }
    if (lane == 31) warp_tot[wid] = incl;
    __syncthreads();
    if (wid == 0 && lane < 8) {                    // scan 8 warp totals
        int wv = warp_tot[lane];
        int wi = wv;
#pragma unroll
        for (int off = 1; off < 8; off <<= 1) {
            int t = __shfl_up_sync(0x000000ff, wi, off);
            if (lane >= off) wi += t;
        }
        warp_tot[lane] = wi - wv;                  // exclusive base per warp
    }
    __syncthreads();
    int run = warp_tot[wid] + (incl - s);          // exclusive base, this thread
#pragma unroll
    for (int k = 0; k < BPT; ++k) {
        const int idx = tid * BPT + k;
        if (idx < NBINS) s_offs[idx] = run + rp[k];   // own-replica offset
        run += tot[k];
    }
    __syncthreads();

    // scatter this CTA's 1024 tokens, atomic-free
    const int4 rv = *reinterpret_cast<const int4*>(g_rank + t0);
    const int rk[4] = { rv.x, rv.y, rv.z, rv.w };
#pragma unroll
    for (int k = 0; k < 4; ++k) {
        const int pos = s_offs[v[k] >> 5] + rk[k];
        __stcg(&g_sorted[pos], make_int2(v[k], t0 + k));
    }
}

// ---- K3: gather (PDL consumer) + bins re-zero ----------------------------
__global__ __launch_bounds__(256) void gather_kernel(
    const float* __restrict__ W,
    const float* __restrict__ bias,
    float*       __restrict__ out)
{
    __shared__ __align__(16) float tile[32][TSTR];
    __shared__ int s_id[32], s_tok[32];

    const int tid   = threadIdx.x;
    const int group = blockIdx.x >> 1;
    const int half  = blockIdx.x & 1;
    const int dim0  = half * HDIM;
    const int w = tid >> 5;          // warp -> dims [16w,16w+16) of half
    const int l = tid & 31;          // lane -> sorted token

    // independent: bias load before the dependency sync
    const float4 bv = __ldg(reinterpret_cast<const float4*>(bias) + half * 32 + l);

#if __CUDA_ARCH__ >= 900
    cudaGridDependencySynchronize();               // wait for g_sorted (K2)
#endif

    // restore invariant: first CTAs zero all replicas (after K2's reads)
    if (blockIdx.x < (NREP * NBINS + 255) / 256) {
        const int idx = blockIdx.x * 256 + tid;
        if (idx < NREP * NBINS) __stcg(&g_bins[idx], 0);
    }

    if (tid < 32) {
        int2 p = g_sorted[group * 32 + tid];
        s_id[tid]  = p.x;
        s_tok[tid] = p.y;
    }
    __syncthreads();

    const int vid = s_id[l];
    const float* wp = W + (size_t)(dim0 + w * 16) * VOCAB + (size_t)vid;
    float rr[16];
#pragma unroll
    for (int j = 0; j < 16; ++j)
        rr[j] = __ldg(wp + (size_t)j * VOCAB);     // coalesced via sort

#pragma unroll
    for (int j = 0; j < 4; ++j) {
        float4 v4 = make_float4(rr[4*j], rr[4*j+1], rr[4*j+2], rr[4*j+3]);
        *reinterpret_cast<float4*>(&tile[l][w * 16 + 4 * j]) = v4;
    }
    __syncthreads();

#pragma unroll
    for (int i = 0; i < 4; ++i) {
        const int t    = w * 4 + i;
        const int orig = s_tok[t];
        float4 v4 = *reinterpret_cast<const float4*>(&tile[t][4 * l]);
        v4.x += bv.x; v4.y += bv.y; v4.z += bv.z; v4.w += bv.w;
        __stcs(reinterpret_cast<float4*>(out + (size_t)orig * EMBED + dim0) + l, v4);
    }
}

// ---- host: PDL-chained launches ------------------------------------------
template <typename K, typename... Args>
static void launch_pdl(K kernel, dim3 grid, dim3 block, Args... args)
{
    cudaLaunchAttribute attr;
    attr.id = cudaLaunchAttributeProgrammaticStreamSerialization;
    attr.val.programmaticStreamSerializationAllowed = 1;
    cudaLaunchConfig_t cfg = {};
    cfg.gridDim  = grid;
    cfg.blockDim = block;
    cfg.attrs    = &attr;
    cfg.numAttrs = 1;
    cfg.stream   = 0;
    cudaLaunchKernelEx(&cfg, kernel, args...);
}

extern "C" void kernel_launch(void* const* d_in, const int* in_sizes, int n_in,
                              void* d_out, int out_size)
{
    const int*   x    = (const int*)d_in[0];
    const float* W    = (const float*)d_in[1];
    const float* bias = (const float*)d_in[2];
    float*       out  = (float*)d_out;

    hist_rank_kernel<<<SCTAS, 256>>>(x);           // 64 CTAs, replica = b&3
    launch_pdl(scan_scatter_kernel, dim3(SCTAS),           dim3(256), x);
    launch_pdl(gather_kernel,       dim3((NTOK / 32) * 2), dim3(256), W, bias, out);
}